// round 13
// baseline (speedup 1.0000x reference)
#include <cuda_runtime.h>
#include <cuda_bf16.h>

// Problem constants
constexpr int B    = 8;
constexpr int C    = 256;
constexpr int L    = 1024;     // 32*32
constexpr int NH   = 8;
constexpr int DK   = 32;
constexpr int DV   = 32;
constexpr int OUTC = 256;
constexpr int TBL  = 63 * 63;
constexpr int BIAS_W = 1280;   // per-CTA Toeplitz window (width 1279, padded)
constexpr float LOG2E = 1.4426950408889634f;

// Scratch (device globals)
__device__ __nv_bfloat16 g_xh[(size_t)B * L * C];   // x^T split  [b][l][c]
__device__ __nv_bfloat16 g_xl[(size_t)B * L * C];
__device__ __nv_bfloat16 g_wh[3 * 256 * 256];       // Q/K/V W^T split [which][n][c]
__device__ __nv_bfloat16 g_wl[3 * 256 * 256];
__device__ __nv_bfloat16 g_fh[256 * 256];           // ffw^T split [n][k]
__device__ __nv_bfloat16 g_fl[256 * 256];
__device__ __nv_bfloat16 g_qh[(size_t)B * NH * L * DK];  // [bh][l][d], pre-scaled by log2e
__device__ __nv_bfloat16 g_ql[(size_t)B * NH * L * DK];
__device__ __nv_bfloat16 g_kh[(size_t)B * NH * L * DK];
__device__ __nv_bfloat16 g_kl[(size_t)B * NH * L * DK];
__device__ float g_vt[(size_t)B * NH * DV * L];          // [bh][d][l], tf32-rounded
__device__ __nv_bfloat16 g_ah[(size_t)B * L * NH * DV];  // attn out split [b][l][h*DV+d]
__device__ __nv_bfloat16 g_al[(size_t)B * L * NH * DV];

// ---------------------------------------------------------------------------
// helpers
// ---------------------------------------------------------------------------
__device__ __forceinline__ unsigned f2tf32(float x) {
    unsigned r;
    asm("cvt.rna.tf32.f32 %0, %1;" : "=r"(r) : "f"(x));
    return r;
}
__device__ __forceinline__ float tf32r(float x) { return __uint_as_float(f2tf32(x)); }
__device__ __forceinline__ float ex2f(float x) {
    float r;
    asm("ex2.approx.f32 %0, %1;" : "=f"(r) : "f"(x));
    return r;
}
__device__ __forceinline__ void mma_tf32(float c[4], const unsigned a[4],
                                         unsigned b0, unsigned b1) {
    asm("mma.sync.aligned.m16n8k8.row.col.f32.tf32.tf32.f32 "
        "{%0,%1,%2,%3}, {%4,%5,%6,%7}, {%8,%9}, {%0,%1,%2,%3};"
        : "+f"(c[0]), "+f"(c[1]), "+f"(c[2]), "+f"(c[3])
        : "r"(a[0]), "r"(a[1]), "r"(a[2]), "r"(a[3]), "r"(b0), "r"(b1));
}
__device__ __forceinline__ void mma_bf16(float c[4], const unsigned a[4],
                                         unsigned b0, unsigned b1) {
    asm("mma.sync.aligned.m16n8k16.row.col.f32.bf16.bf16.f32 "
        "{%0,%1,%2,%3}, {%4,%5,%6,%7}, {%8,%9}, {%0,%1,%2,%3};"
        : "+f"(c[0]), "+f"(c[1]), "+f"(c[2]), "+f"(c[3])
        : "r"(a[0]), "r"(a[1]), "r"(a[2]), "r"(a[3]), "r"(b0), "r"(b1));
}
__device__ __forceinline__ void ldsm4(unsigned r[4], unsigned addr) {
    asm volatile("ldmatrix.sync.aligned.m8n8.x4.shared.b16 {%0,%1,%2,%3}, [%4];"
                 : "=r"(r[0]), "=r"(r[1]), "=r"(r[2]), "=r"(r[3]) : "r"(addr));
}
__device__ __forceinline__ unsigned smem_u32(const void* p) {
    return (unsigned)__cvta_generic_to_shared(p);
}
__device__ __forceinline__ void cp16(void* smem, const void* gmem) {
    asm volatile("cp.async.cg.shared.global [%0], [%1], 16;"
                 :: "r"(smem_u32(smem)), "l"(gmem));
}
__device__ __forceinline__ void cp_commit() {
    asm volatile("cp.async.commit_group;");
}
template <int N> __device__ __forceinline__ void cp_wait() {
    asm volatile("cp.async.wait_group %0;" :: "n"(N));
}
__device__ __forceinline__ void bsplit2(float v0, float v1, unsigned& hi, unsigned& lo) {
    __nv_bfloat16 h0 = __float2bfloat16(v0);
    __nv_bfloat16 h1 = __float2bfloat16(v1);
    __nv_bfloat16 l0 = __float2bfloat16(v0 - __bfloat162float(h0));
    __nv_bfloat16 l1 = __float2bfloat16(v1 - __bfloat162float(h1));
    hi = (unsigned)__bfloat16_as_ushort(h0) | ((unsigned)__bfloat16_as_ushort(h1) << 16);
    lo = (unsigned)__bfloat16_as_ushort(l0) | ((unsigned)__bfloat16_as_ushort(l1) << 16);
}

// ---------------------------------------------------------------------------
// Kernel 0: prep — transpose + bf16 hi/lo split of x and the 4 weight matrices.
// ---------------------------------------------------------------------------
__global__ __launch_bounds__(256) void prep_kernel(
    const float* __restrict__ x,  const float* __restrict__ Qw,
    const float* __restrict__ Kw, const float* __restrict__ Vw,
    const float* __restrict__ ffw)
{
    __shared__ float t[32][36];
    const int bid = blockIdx.x;
    const int tid = threadIdx.x;

    if (bid < 2048) {                 // x part: 256 tiles per batch
        const int b  = bid >> 8;
        const int r  = bid & 255;
        const int ct = r >> 5;
        const int lt = r & 31;
        {
            int i = tid >> 3, j4 = tid & 7;
            *(float4*)&t[i][j4 * 4] =
                *(const float4*)&x[((size_t)b * C + ct * 32 + i) * L + lt * 32 + j4 * 4];
        }
        __syncthreads();
#pragma unroll
        for (int it = 0; it < 2; it++) {
            int s = tid + it * 256;
            int l = s >> 4, c2 = (s & 15) * 2;
            unsigned hi, lo;
            bsplit2(t[c2][l], t[c2 + 1][l], hi, lo);
            size_t o = ((size_t)b * L + lt * 32 + l) * C + ct * 32 + c2;
            *(unsigned*)&g_xh[o] = hi;
            *(unsigned*)&g_xl[o] = lo;
        }
    } else {                          // weight part
        const int r     = bid - 2048;
        const int which = r >> 6;
        const int rr    = r & 63;
        const int ct    = rr >> 3;
        const int nt    = rr & 7;
        const float* Wm = (which == 0) ? Qw : (which == 1) ? Kw
                        : (which == 2) ? Vw : ffw;
        __nv_bfloat16* oh = (which == 3) ? g_fh : g_wh + (size_t)which * 256 * 256;
        __nv_bfloat16* ol = (which == 3) ? g_fl : g_wl + (size_t)which * 256 * 256;
        {
            int i = tid >> 3, j4 = tid & 7;
            *(float4*)&t[i][j4 * 4] =
                *(const float4*)&Wm[((size_t)(ct * 32 + i)) * 256 + nt * 32 + j4 * 4];
        }
        __syncthreads();
#pragma unroll
        for (int it = 0; it < 2; it++) {
            int s = tid + it * 256;
            int n = s >> 4, c2 = (s & 15) * 2;
            unsigned hi, lo;
            bsplit2(t[c2][n], t[c2 + 1][n], hi, lo);
            size_t o = ((size_t)(nt * 32 + n)) * 256 + ct * 32 + c2;
            *(unsigned*)&oh[o] = hi;
            *(unsigned*)&ol[o] = lo;
        }
    }
}

constexpr int AP = 40;   // bf16 smem pitch (80B rows)

// ---------------------------------------------------------------------------
// Shared bf16x3 GEMM body: C[128x64] = A[128x256] @ B[64x256]^T.
// cp.async 2-stage pipeline, one __syncthreads per k-iteration.
// ---------------------------------------------------------------------------
struct GemmSmem {
    __nv_bfloat16 Ah[2][128 * AP];
    __nv_bfloat16 Al[2][128 * AP];
    __nv_bfloat16 Bh[2][64 * AP];
    __nv_bfloat16 Bl[2][64 * AP];
};

__device__ __forceinline__ void gemm_bf16x3(
    GemmSmem& S, float acc[2][4][4],
    const __nv_bfloat16* __restrict__ Asrc_h, const __nv_bfloat16* __restrict__ Asrc_l,
    const __nv_bfloat16* __restrict__ Bsrc_h, const __nv_bfloat16* __restrict__ Bsrc_l,
    int m0, int n0)
{
    const int tid  = threadIdx.x;
    const int warp = tid >> 5;
    const int lane = tid & 31;
    const int wm   = warp >> 1;
    const int wn   = warp & 1;
    const int lt   = lane >> 3;
    const int lr   = lane & 7;

    const int am = tid >> 2, ac8 = (tid & 3) * 8;

    auto load = [&](int k0, int bb) {
        cp16(&S.Ah[bb][am * AP + ac8],        &Asrc_h[(size_t)(m0 + am) * 256 + k0 + ac8]);
        cp16(&S.Ah[bb][(am + 64) * AP + ac8], &Asrc_h[(size_t)(m0 + am + 64) * 256 + k0 + ac8]);
        cp16(&S.Al[bb][am * AP + ac8],        &Asrc_l[(size_t)(m0 + am) * 256 + k0 + ac8]);
        cp16(&S.Al[bb][(am + 64) * AP + ac8], &Asrc_l[(size_t)(m0 + am + 64) * 256 + k0 + ac8]);
        cp16(&S.Bh[bb][am * AP + ac8],        &Bsrc_h[(size_t)(n0 + am) * 256 + k0 + ac8]);
        cp16(&S.Bl[bb][am * AP + ac8],        &Bsrc_l[(size_t)(n0 + am) * 256 + k0 + ac8]);
    };

    load(0, 0);
    cp_commit();

    for (int kt = 0; kt < 8; kt++) {
        cp_wait<0>();
        __syncthreads();
        if (kt < 7) {
            load((kt + 1) * 32, (kt + 1) & 1);
            cp_commit();
        }
        const int bb = kt & 1;

#pragma unroll
        for (int kc = 0; kc < 32; kc += 16) {
            unsigned ah[2][4], al[2][4];
#pragma unroll
            for (int mt = 0; mt < 2; mt++) {
                int row = wm * 32 + mt * 16 + (lt & 1) * 8 + lr;
                int col = kc + (lt >> 1) * 8;
                ldsm4(ah[mt], smem_u32(&S.Ah[bb][row * AP + col]));
                ldsm4(al[mt], smem_u32(&S.Al[bb][row * AP + col]));
            }
#pragma unroll
            for (int np = 0; np < 2; np++) {
                unsigned bhf[4], blf[4];
                int row = wn * 32 + np * 16 + (lt >> 1) * 8 + lr;
                int col = kc + (lt & 1) * 8;
                ldsm4(bhf, smem_u32(&S.Bh[bb][row * AP + col]));
                ldsm4(blf, smem_u32(&S.Bl[bb][row * AP + col]));
#pragma unroll
                for (int mt = 0; mt < 2; mt++)
#pragma unroll
                    for (int sub = 0; sub < 2; sub++)
                        mma_bf16(acc[mt][np * 2 + sub], ah[mt], bhf[sub * 2], bhf[sub * 2 + 1]);
#pragma unroll
                for (int mt = 0; mt < 2; mt++)
#pragma unroll
                    for (int sub = 0; sub < 2; sub++)
                        mma_bf16(acc[mt][np * 2 + sub], ah[mt], blf[sub * 2], blf[sub * 2 + 1]);
#pragma unroll
                for (int mt = 0; mt < 2; mt++)
#pragma unroll
                    for (int sub = 0; sub < 2; sub++)
                        mma_bf16(acc[mt][np * 2 + sub], al[mt], bhf[sub * 2], bhf[sub * 2 + 1]);
            }
        }
    }
}

// ---------------------------------------------------------------------------
// Kernel 1: QKV projections, bf16x3 mma, 3 CTAs/SM. Q pre-scaled by log2(e).
// ---------------------------------------------------------------------------
__global__ __launch_bounds__(256, 3) void qkv_mma()
{
    __shared__ GemmSmem S;

    const int bz    = blockIdx.z;
    const int b     = bz / 3;
    const int which = bz % 3;
    const int m0    = blockIdx.x * 128;
    const int n0    = blockIdx.y * 64;

    float acc[2][4][4] = {};
    gemm_bf16x3(S, acc,
                g_xh + (size_t)b * L * C, g_xl + (size_t)b * L * C,
                g_wh + (size_t)which * 256 * 256, g_wl + (size_t)which * 256 * 256,
                m0, n0);

    const int tid  = threadIdx.x;
    const int warp = tid >> 5;
    const int lane = tid & 31;
    const int gq   = lane >> 2;
    const int cq   = lane & 3;
    const int wm   = warp >> 1;
    const int wn   = warp & 1;

    const int h = (n0 >> 5) + wn;
    if (which < 2) {
        const float scale = (which == 0) ? LOG2E : 1.0f;
        __nv_bfloat16* oh = ((which == 0) ? g_qh : g_kh) + (size_t)(b * NH + h) * L * DK;
        __nv_bfloat16* ol = ((which == 0) ? g_ql : g_kl) + (size_t)(b * NH + h) * L * DK;
#pragma unroll
        for (int mt = 0; mt < 2; mt++)
#pragma unroll
            for (int nt = 0; nt < 4; nt++) {
                int d = nt * 8 + cq * 2;
#pragma unroll
                for (int rs = 0; rs < 2; rs++) {
                    int gm = m0 + wm * 32 + mt * 16 + gq + rs * 8;
                    unsigned hi, lo;
                    bsplit2(acc[mt][nt][rs * 2] * scale,
                            acc[mt][nt][rs * 2 + 1] * scale, hi, lo);
                    *(unsigned*)&oh[(size_t)gm * DK + d] = hi;
                    *(unsigned*)&ol[(size_t)gm * DK + d] = lo;
                }
            }
    } else {
        float* ov = g_vt + (size_t)(b * NH + h) * DV * L;
#pragma unroll
        for (int mt = 0; mt < 2; mt++)
#pragma unroll
            for (int nt = 0; nt < 4; nt++)
#pragma unroll
                for (int rs = 0; rs < 2; rs++) {
                    int gm = m0 + wm * 32 + mt * 16 + gq + rs * 8;
                    int d  = nt * 8 + cq * 2;
                    ov[(size_t)d * L + gm]       = tf32r(acc[mt][nt][rs * 2]);
                    ov[(size_t)(d + 1) * L + gm] = tf32r(acc[mt][nt][rs * 2 + 1]);
                }
    }
}

// ---------------------------------------------------------------------------
// Kernel 2: flash attention, FAT WARPS: Br=256 per CTA, 8 warps x 32 q-rows
// (unchanged from R11 winner).
// ---------------------------------------------------------------------------
__global__ __launch_bounds__(256, 2) void attn_mma(const float* __restrict__ rel_bias)
{
    constexpr int KP = 40;   // bf16 pitch
    constexpr int VP = 68;   // fp32 pitch
    struct Tile {
        __nv_bfloat16 kh[64 * KP];   // 5120 B
        __nv_bfloat16 kl[64 * KP];   // 5120 B
        float         vt[32 * VP];   // 8704 B
    };
    __shared__ float bias_s[BIAS_W];
    __shared__ __align__(16) Tile tiles[2];

    const int bh = blockIdx.y;
    const int h  = bh & 7;
    const int b  = bh >> 3;
    const __nv_bfloat16* qh_g = g_qh + (size_t)bh * L * DK;
    const __nv_bfloat16* ql_g = g_ql + (size_t)bh * L * DK;
    const __nv_bfloat16* kh_g = g_kh + (size_t)bh * L * DK;
    const __nv_bfloat16* kl_g = g_kl + (size_t)bh * L * DK;
    const float*         vt_g = g_vt + (size_t)bh * DV * L;

    const int tid  = threadIdx.x;
    const int warp = tid >> 5;
    const int lane = tid & 31;
    const int g    = lane >> 2;
    const int c    = lane & 3;
    const int lt   = lane >> 3;
    const int lr   = lane & 7;
    const int i0   = blockIdx.x * 256;

    // Start tile-0 staging immediately (independent of q/bias loads).
    const int krow = tid >> 2, kc8 = (tid & 3) * 8;
    const int vd0  = tid >> 4, vj4 = (tid & 15) * 4;
    auto load_tile = [&](int j0, Tile& T) {
        cp16(&T.kh[krow * KP + kc8], &kh_g[(size_t)(j0 + krow) * DK + kc8]);
        cp16(&T.kl[krow * KP + kc8], &kl_g[(size_t)(j0 + krow) * DK + kc8]);
        cp16(&T.vt[vd0 * VP + vj4],        &vt_g[(size_t)vd0 * L + j0 + vj4]);
        cp16(&T.vt[(vd0 + 16) * VP + vj4], &vt_g[(size_t)(vd0 + 16) * L + j0 + vj4]);
    };
    load_tile(0, tiles[0]);
    cp_commit();

    // Compact Toeplitz bias window: idx = j - (i0+r) + 1056, r in [0,256).
    // Staged u = j - r + 255 in [0, 1278]; idx = u + (801 - i0).
    {
        const float* bsrc = rel_bias + (size_t)h * TBL + (801 - i0);
        for (int u = tid; u < BIAS_W; u += 256)
            bias_s[u] = bsrc[u] * LOG2E;
    }

    // q fragments direct from gmem (one-time LDG.32s)
    unsigned qh[2][2][4], ql[2][2][4];   // [mt][kc][frag]
#pragma unroll
    for (int mt = 0; mt < 2; mt++) {
        const int r0 = i0 + warp * 32 + mt * 16 + g;
#pragma unroll
        for (int kc = 0; kc < 2; kc++) {
            int col = kc * 16 + 2 * c;
            qh[mt][kc][0] = *(const unsigned*)&qh_g[(size_t)r0 * DK + col];
            qh[mt][kc][1] = *(const unsigned*)&qh_g[(size_t)(r0 + 8) * DK + col];
            qh[mt][kc][2] = *(const unsigned*)&qh_g[(size_t)r0 * DK + col + 8];
            qh[mt][kc][3] = *(const unsigned*)&qh_g[(size_t)(r0 + 8) * DK + col + 8];
            ql[mt][kc][0] = *(const unsigned*)&ql_g[(size_t)r0 * DK + col];
            ql[mt][kc][1] = *(const unsigned*)&ql_g[(size_t)(r0 + 8) * DK + col];
            ql[mt][kc][2] = *(const unsigned*)&ql_g[(size_t)r0 * DK + col + 8];
            ql[mt][kc][3] = *(const unsigned*)&ql_g[(size_t)(r0 + 8) * DK + col + 8];
        }
    }

    float lsum[2][2] = {};
    float o[2][4][4] = {};
    int ubase[2];
#pragma unroll
    for (int mt = 0; mt < 2; mt++)
        ubase[mt] = 255 - (warp * 32 + mt * 16 + g) + 2 * c;

    for (int jt = 0; jt < 16; jt++) {
        const int j0 = jt * 64;
        cp_wait<0>();
        __syncthreads();
        if (jt < 15) {
            load_tile(j0 + 64, tiles[(jt + 1) & 1]);
            cp_commit();
        }
        Tile& T = tiles[jt & 1];

#pragma unroll
        for (int half = 0; half < 2; half++) {
            float s[2][4][4];
#pragma unroll
            for (int mt = 0; mt < 2; mt++)
#pragma unroll
                for (int nt4 = 0; nt4 < 4; nt4++) {
                    int u0 = j0 + (half * 4 + nt4) * 8 + ubase[mt];
                    s[mt][nt4][0] = bias_s[u0];
                    s[mt][nt4][1] = bias_s[u0 + 1];
                    s[mt][nt4][2] = bias_s[u0 - 8];
                    s[mt][nt4][3] = bias_s[u0 - 7];
                }
#pragma unroll
            for (int kc = 0; kc < 2; kc++)
#pragma unroll
                for (int np2 = 0; np2 < 2; np2++) {
                    unsigned bhf[4], blf[4];
                    int row = (half * 2 + np2) * 16 + (lt >> 1) * 8 + lr;
                    int col = kc * 16 + (lt & 1) * 8;
                    ldsm4(bhf, smem_u32(&T.kh[row * KP + col]));
                    ldsm4(blf, smem_u32(&T.kl[row * KP + col]));
#pragma unroll
                    for (int mt = 0; mt < 2; mt++) {
                        float* sp0 = s[mt][np2 * 2];
                        float* sp1 = s[mt][np2 * 2 + 1];
                        mma_bf16(sp0, qh[mt][kc], bhf[0], bhf[1]);
                        mma_bf16(sp1, qh[mt][kc], bhf[2], bhf[3]);
                        mma_bf16(sp0, qh[mt][kc], blf[0], blf[1]);
                        mma_bf16(sp1, qh[mt][kc], blf[2], blf[3]);
                        mma_bf16(sp0, ql[mt][kc], bhf[0], bhf[1]);
                        mma_bf16(sp1, ql[mt][kc], bhf[2], bhf[3]);
                    }
                }

#pragma unroll
            for (int mt = 0; mt < 2; mt++)
#pragma unroll
                for (int nt4 = 0; nt4 < 4; nt4++) {
                    s[mt][nt4][0] = ex2f(s[mt][nt4][0]);
                    s[mt][nt4][1] = ex2f(s[mt][nt4][1]);
                    s[mt][nt4][2] = ex2f(s[mt][nt4][2]);
                    s[mt][nt4][3] = ex2f(s[mt][nt4][3]);
                    lsum[mt][0] += s[mt][nt4][0] + s[mt][nt4][1];
                    lsum[mt][1] += s[mt][nt4][2] + s[mt][nt4][3];
                }

#pragma unroll
            for (int j2 = 0; j2 < 4; j2++) {
                unsigned a0[4] = {__float_as_uint(s[0][j2][0]), __float_as_uint(s[0][j2][2]),
                                  __float_as_uint(s[0][j2][1]), __float_as_uint(s[0][j2][3])};
                unsigned a1[4] = {__float_as_uint(s[1][j2][0]), __float_as_uint(s[1][j2][2]),
                                  __float_as_uint(s[1][j2][1]), __float_as_uint(s[1][j2][3])};
#pragma unroll
                for (int dt = 0; dt < 4; dt++) {
                    float2 vv2 = *(const float2*)
                        &T.vt[(dt * 8 + g) * VP + half * 32 + j2 * 8 + 2 * c];
                    unsigned v0 = __float_as_uint(vv2.x), v1 = __float_as_uint(vv2.y);
                    mma_tf32(o[0][dt], a0, v0, v1);
                    mma_tf32(o[1][dt], a1, v0, v1);
                }
            }
        }
    }

#pragma unroll
    for (int mt = 0; mt < 2; mt++) {
        lsum[mt][0] += __shfl_xor_sync(0xffffffffu, lsum[mt][0], 1);
        lsum[mt][0] += __shfl_xor_sync(0xffffffffu, lsum[mt][0], 2);
        lsum[mt][1] += __shfl_xor_sync(0xffffffffu, lsum[mt][1], 1);
        lsum[mt][1] += __shfl_xor_sync(0xffffffffu, lsum[mt][1], 2);
        float inv0 = 1.0f / lsum[mt][0];
        float inv1 = 1.0f / lsum[mt][1];

        size_t row0 = (size_t)(b * L + i0 + warp * 32 + mt * 16 + g) * (NH * DV) + h * DV;
        size_t row1 = row0 + (size_t)8 * (NH * DV);
#pragma unroll
        for (int dt = 0; dt < 4; dt++) {
            unsigned hi, lo;
            bsplit2(o[mt][dt][0] * inv0, o[mt][dt][1] * inv0, hi, lo);
            *(unsigned*)&g_ah[row0 + dt * 8 + 2 * c] = hi;
            *(unsigned*)&g_al[row0 + dt * 8 + 2 * c] = lo;
            bsplit2(o[mt][dt][2] * inv1, o[mt][dt][3] * inv1, hi, lo);
            *(unsigned*)&g_ah[row1 + dt * 8 + 2 * c] = hi;
            *(unsigned*)&g_al[row1 + dt * 8 + 2 * c] = lo;
        }
    }
}

// ---------------------------------------------------------------------------
// Kernel 3: FF projection, bf16x3 mma, 128x64 tiles (same body as qkv),
// 3 CTAs/SM, fused bias + transposed store.
// ---------------------------------------------------------------------------
__global__ __launch_bounds__(256, 3) void ff_mma(
    const float* __restrict__ ffb,
    float* __restrict__ out)
{
    __shared__ GemmSmem S;

    const int m0 = blockIdx.x * 128;  // row in (B*L)
    const int n0 = blockIdx.y * 64;

    float acc[2][4][4] = {};
    gemm_bf16x3(S, acc, g_ah, g_al, g_fh, g_fl, m0, n0);

    const int tid  = threadIdx.x;
    const int warp = tid >> 5;
    const int lane = tid & 31;
    const int gq   = lane >> 2;
    const int cq   = lane & 3;
    const int wm   = warp >> 1;
    const int wn   = warp & 1;

    const int bb  = m0 >> 10;
    const int l00 = m0 & 1023;
#pragma unroll
    for (int nt = 0; nt < 4; nt++)
#pragma unroll
        for (int e = 0; e < 2; e++) {
            int gn = n0 + wn * 32 + nt * 8 + cq * 2 + e;
            float bias = ffb[gn];
            float* dst = out + ((size_t)(bb * OUTC + gn)) * L + l00 + wm * 32;
#pragma unroll
            for (int mt = 0; mt < 2; mt++)
#pragma unroll
                for (int rs = 0; rs < 2; rs++)
                    dst[mt * 16 + rs * 8 + gq] = acc[mt][nt][rs * 2 + e] + bias;
        }
}

// ---------------------------------------------------------------------------
extern "C" void kernel_launch(void* const* d_in, const int* in_sizes, int n_in,
                              void* d_out, int out_size)
{
    const float* x        = (const float*)d_in[0];
    const float* Qw       = (const float*)d_in[1];
    const float* Kw       = (const float*)d_in[2];
    const float* Vw       = (const float*)d_in[3];
    const float* ffw      = (const float*)d_in[4];
    const float* ffb      = (const float*)d_in[5];
    const float* rel_bias = (const float*)d_in[6];
    float* out = (float*)d_out;

    prep_kernel<<<2048 + 256, 256>>>(x, Qw, Kw, Vw, ffw);
    qkv_mma<<<dim3(L / 128, 4, B * 3), 256>>>();
    attn_mma<<<dim3(L / 256, B * NH), 256>>>(rel_bias);
    ff_mma<<<dim3((B * L) / 128, OUTC / 64), 256>>>(ffb, out);
}

// round 15
// speedup vs baseline: 1.0145x; 1.0145x over previous
#include <cuda_runtime.h>
#include <cuda_bf16.h>

// Problem constants
constexpr int B    = 8;
constexpr int C    = 256;
constexpr int L    = 1024;     // 32*32
constexpr int NH   = 8;
constexpr int DK   = 32;
constexpr int DV   = 32;
constexpr int OUTC = 256;
constexpr int TBL  = 63 * 63;
constexpr int BIAS_W = 1280;   // per-CTA Toeplitz window (width 1279, padded)
constexpr float LOG2E = 1.4426950408889634f;

// Scratch (device globals)
__device__ __nv_bfloat16 g_xh[(size_t)B * L * C];   // x^T split  [b][l][c]
__device__ __nv_bfloat16 g_xl[(size_t)B * L * C];
__device__ __nv_bfloat16 g_wh[3 * 256 * 256];       // Q/K/V W^T split [which][n][c]
__device__ __nv_bfloat16 g_wl[3 * 256 * 256];
__device__ __nv_bfloat16 g_fh[256 * 256];           // ffw^T split [n][k]
__device__ __nv_bfloat16 g_fl[256 * 256];
__device__ __nv_bfloat16 g_qh[(size_t)B * NH * L * DK];  // [bh][l][d], pre-scaled by log2e
__device__ __nv_bfloat16 g_ql[(size_t)B * NH * L * DK];
__device__ __nv_bfloat16 g_kh[(size_t)B * NH * L * DK];
__device__ __nv_bfloat16 g_kl[(size_t)B * NH * L * DK];
__device__ float g_vt[(size_t)B * NH * DV * L];          // [bh][d][l], tf32-rounded
__device__ __nv_bfloat16 g_ah[(size_t)B * L * NH * DV];  // attn out split [b][l][h*DV+d]
__device__ __nv_bfloat16 g_al[(size_t)B * L * NH * DV];

// ---------------------------------------------------------------------------
// helpers
// ---------------------------------------------------------------------------
__device__ __forceinline__ unsigned f2tf32(float x) {
    unsigned r;
    asm("cvt.rna.tf32.f32 %0, %1;" : "=r"(r) : "f"(x));
    return r;
}
__device__ __forceinline__ float tf32r(float x) { return __uint_as_float(f2tf32(x)); }
__device__ __forceinline__ float ex2f(float x) {
    float r;
    asm("ex2.approx.f32 %0, %1;" : "=f"(r) : "f"(x));
    return r;
}
__device__ __forceinline__ void mma_tf32(float c[4], const unsigned a[4],
                                         unsigned b0, unsigned b1) {
    asm("mma.sync.aligned.m16n8k8.row.col.f32.tf32.tf32.f32 "
        "{%0,%1,%2,%3}, {%4,%5,%6,%7}, {%8,%9}, {%0,%1,%2,%3};"
        : "+f"(c[0]), "+f"(c[1]), "+f"(c[2]), "+f"(c[3])
        : "r"(a[0]), "r"(a[1]), "r"(a[2]), "r"(a[3]), "r"(b0), "r"(b1));
}
__device__ __forceinline__ void mma_bf16(float c[4], const unsigned a[4],
                                         unsigned b0, unsigned b1) {
    asm("mma.sync.aligned.m16n8k16.row.col.f32.bf16.bf16.f32 "
        "{%0,%1,%2,%3}, {%4,%5,%6,%7}, {%8,%9}, {%0,%1,%2,%3};"
        : "+f"(c[0]), "+f"(c[1]), "+f"(c[2]), "+f"(c[3])
        : "r"(a[0]), "r"(a[1]), "r"(a[2]), "r"(a[3]), "r"(b0), "r"(b1));
}
__device__ __forceinline__ void ldsm4(unsigned r[4], unsigned addr) {
    asm volatile("ldmatrix.sync.aligned.m8n8.x4.shared.b16 {%0,%1,%2,%3}, [%4];"
                 : "=r"(r[0]), "=r"(r[1]), "=r"(r[2]), "=r"(r[3]) : "r"(addr));
}
__device__ __forceinline__ unsigned smem_u32(const void* p) {
    return (unsigned)__cvta_generic_to_shared(p);
}
__device__ __forceinline__ void cp16(void* smem, const void* gmem) {
    asm volatile("cp.async.cg.shared.global [%0], [%1], 16;"
                 :: "r"(smem_u32(smem)), "l"(gmem));
}
__device__ __forceinline__ void cp_commit() {
    asm volatile("cp.async.commit_group;");
}
template <int N> __device__ __forceinline__ void cp_wait() {
    asm volatile("cp.async.wait_group %0;" :: "n"(N));
}
__device__ __forceinline__ void bsplit2(float v0, float v1, unsigned& hi, unsigned& lo) {
    __nv_bfloat16 h0 = __float2bfloat16(v0);
    __nv_bfloat16 h1 = __float2bfloat16(v1);
    __nv_bfloat16 l0 = __float2bfloat16(v0 - __bfloat162float(h0));
    __nv_bfloat16 l1 = __float2bfloat16(v1 - __bfloat162float(h1));
    hi = (unsigned)__bfloat16_as_ushort(h0) | ((unsigned)__bfloat16_as_ushort(h1) << 16);
    lo = (unsigned)__bfloat16_as_ushort(l0) | ((unsigned)__bfloat16_as_ushort(l1) << 16);
}

// ---------------------------------------------------------------------------
// Kernel 0: prep — transpose + bf16 hi/lo split of x and the 4 weight matrices.
// ---------------------------------------------------------------------------
__global__ __launch_bounds__(256) void prep_kernel(
    const float* __restrict__ x,  const float* __restrict__ Qw,
    const float* __restrict__ Kw, const float* __restrict__ Vw,
    const float* __restrict__ ffw)
{
    __shared__ float t[32][36];
    const int bid = blockIdx.x;
    const int tid = threadIdx.x;

    if (bid < 2048) {                 // x part: 256 tiles per batch
        const int b  = bid >> 8;
        const int r  = bid & 255;
        const int ct = r >> 5;
        const int lt = r & 31;
        {
            int i = tid >> 3, j4 = tid & 7;
            *(float4*)&t[i][j4 * 4] =
                *(const float4*)&x[((size_t)b * C + ct * 32 + i) * L + lt * 32 + j4 * 4];
        }
        __syncthreads();
#pragma unroll
        for (int it = 0; it < 2; it++) {
            int s = tid + it * 256;
            int l = s >> 4, c2 = (s & 15) * 2;
            unsigned hi, lo;
            bsplit2(t[c2][l], t[c2 + 1][l], hi, lo);
            size_t o = ((size_t)b * L + lt * 32 + l) * C + ct * 32 + c2;
            *(unsigned*)&g_xh[o] = hi;
            *(unsigned*)&g_xl[o] = lo;
        }
    } else {                          // weight part
        const int r     = bid - 2048;
        const int which = r >> 6;
        const int rr    = r & 63;
        const int ct    = rr >> 3;
        const int nt    = rr & 7;
        const float* Wm = (which == 0) ? Qw : (which == 1) ? Kw
                        : (which == 2) ? Vw : ffw;
        __nv_bfloat16* oh = (which == 3) ? g_fh : g_wh + (size_t)which * 256 * 256;
        __nv_bfloat16* ol = (which == 3) ? g_fl : g_wl + (size_t)which * 256 * 256;
        {
            int i = tid >> 3, j4 = tid & 7;
            *(float4*)&t[i][j4 * 4] =
                *(const float4*)&Wm[((size_t)(ct * 32 + i)) * 256 + nt * 32 + j4 * 4];
        }
        __syncthreads();
#pragma unroll
        for (int it = 0; it < 2; it++) {
            int s = tid + it * 256;
            int n = s >> 4, c2 = (s & 15) * 2;
            unsigned hi, lo;
            bsplit2(t[c2][n], t[c2 + 1][n], hi, lo);
            size_t o = ((size_t)(nt * 32 + n)) * 256 + ct * 32 + c2;
            *(unsigned*)&oh[o] = hi;
            *(unsigned*)&ol[o] = lo;
        }
    }
}

constexpr int AP = 40;   // bf16 smem pitch (80B rows)

// ---------------------------------------------------------------------------
// Fat bf16x3 GEMM body: C[128x128] = A[128x256] @ B[128x256]^T.
// 8 warps as 4(wm, 32 rows) x 2(wn, 64 cols); 48 mma per 12 ldsm per kc.
// cp.async 2-stage pipeline, one __syncthreads per k-iteration.
// Dynamic smem: 80 KB.
// ---------------------------------------------------------------------------
struct Gemm2Smem {
    __nv_bfloat16 Ah[2][128 * AP];
    __nv_bfloat16 Al[2][128 * AP];
    __nv_bfloat16 Bh[2][128 * AP];
    __nv_bfloat16 Bl[2][128 * AP];
};
constexpr unsigned GEMM2_SMEM = sizeof(Gemm2Smem);   // 81920 B

__device__ __forceinline__ void gemm2_bf16x3(
    Gemm2Smem& S, float acc[2][8][4],
    const __nv_bfloat16* __restrict__ Asrc_h, const __nv_bfloat16* __restrict__ Asrc_l,
    const __nv_bfloat16* __restrict__ Bsrc_h, const __nv_bfloat16* __restrict__ Bsrc_l,
    int m0, int n0)
{
    const int tid  = threadIdx.x;
    const int warp = tid >> 5;
    const int lane = tid & 31;
    const int wm   = warp >> 1;       // 0..3, 32-row tiles
    const int wn   = warp & 1;        // 0..1, 64-col tiles
    const int lt   = lane >> 3;
    const int lr   = lane & 7;

    const int am = tid >> 2, ac8 = (tid & 3) * 8;

    auto load = [&](int k0, int bb) {
        cp16(&S.Ah[bb][am * AP + ac8],        &Asrc_h[(size_t)(m0 + am) * 256 + k0 + ac8]);
        cp16(&S.Ah[bb][(am + 64) * AP + ac8], &Asrc_h[(size_t)(m0 + am + 64) * 256 + k0 + ac8]);
        cp16(&S.Al[bb][am * AP + ac8],        &Asrc_l[(size_t)(m0 + am) * 256 + k0 + ac8]);
        cp16(&S.Al[bb][(am + 64) * AP + ac8], &Asrc_l[(size_t)(m0 + am + 64) * 256 + k0 + ac8]);
        cp16(&S.Bh[bb][am * AP + ac8],        &Bsrc_h[(size_t)(n0 + am) * 256 + k0 + ac8]);
        cp16(&S.Bh[bb][(am + 64) * AP + ac8], &Bsrc_h[(size_t)(n0 + am + 64) * 256 + k0 + ac8]);
        cp16(&S.Bl[bb][am * AP + ac8],        &Bsrc_l[(size_t)(n0 + am) * 256 + k0 + ac8]);
        cp16(&S.Bl[bb][(am + 64) * AP + ac8], &Bsrc_l[(size_t)(n0 + am + 64) * 256 + k0 + ac8]);
    };

    load(0, 0);
    cp_commit();

    for (int kt = 0; kt < 8; kt++) {
        cp_wait<0>();
        __syncthreads();
        if (kt < 7) {
            load((kt + 1) * 32, (kt + 1) & 1);
            cp_commit();
        }
        const int bb = kt & 1;

#pragma unroll
        for (int kc = 0; kc < 32; kc += 16) {
            unsigned ah[2][4], al[2][4];
#pragma unroll
            for (int mt = 0; mt < 2; mt++) {
                int row = wm * 32 + mt * 16 + (lt & 1) * 8 + lr;
                int col = kc + (lt >> 1) * 8;
                ldsm4(ah[mt], smem_u32(&S.Ah[bb][row * AP + col]));
                ldsm4(al[mt], smem_u32(&S.Al[bb][row * AP + col]));
            }
#pragma unroll
            for (int np = 0; np < 4; np++) {
                unsigned bhf[4], blf[4];
                int row = wn * 64 + np * 16 + (lt >> 1) * 8 + lr;
                int col = kc + (lt & 1) * 8;
                ldsm4(bhf, smem_u32(&S.Bh[bb][row * AP + col]));
                ldsm4(blf, smem_u32(&S.Bl[bb][row * AP + col]));
#pragma unroll
                for (int mt = 0; mt < 2; mt++)
#pragma unroll
                    for (int sub = 0; sub < 2; sub++)
                        mma_bf16(acc[mt][np * 2 + sub], ah[mt], bhf[sub * 2], bhf[sub * 2 + 1]);
#pragma unroll
                for (int mt = 0; mt < 2; mt++)
#pragma unroll
                    for (int sub = 0; sub < 2; sub++)
                        mma_bf16(acc[mt][np * 2 + sub], ah[mt], blf[sub * 2], blf[sub * 2 + 1]);
#pragma unroll
                for (int mt = 0; mt < 2; mt++)
#pragma unroll
                    for (int sub = 0; sub < 2; sub++)
                        mma_bf16(acc[mt][np * 2 + sub], al[mt], bhf[sub * 2], bhf[sub * 2 + 1]);
            }
        }
    }
}

// ---------------------------------------------------------------------------
// Kernel 1: QKV projections, fat bf16x3 gemm (128x128). Q pre-scaled by log2e.
// grid (L/128, 256/128, B*3).
// ---------------------------------------------------------------------------
__global__ __launch_bounds__(256, 2) void qkv_mma()
{
    extern __shared__ __align__(16) char dsm[];
    Gemm2Smem& S = *(Gemm2Smem*)dsm;

    const int bz    = blockIdx.z;
    const int b     = bz / 3;
    const int which = bz % 3;
    const int m0    = blockIdx.x * 128;
    const int n0    = blockIdx.y * 128;

    float acc[2][8][4] = {};
    gemm2_bf16x3(S, acc,
                 g_xh + (size_t)b * L * C, g_xl + (size_t)b * L * C,
                 g_wh + (size_t)which * 256 * 256, g_wl + (size_t)which * 256 * 256,
                 m0, n0);

    const int tid  = threadIdx.x;
    const int warp = tid >> 5;
    const int lane = tid & 31;
    const int gq   = lane >> 2;
    const int cq   = lane & 3;
    const int wm   = warp >> 1;
    const int wn   = warp & 1;

    if (which < 2) {
        const float scale = (which == 0) ? LOG2E : 1.0f;
        __nv_bfloat16* ohg = (which == 0) ? g_qh : g_kh;
        __nv_bfloat16* olg = (which == 0) ? g_ql : g_kl;
#pragma unroll
        for (int mt = 0; mt < 2; mt++)
#pragma unroll
            for (int nt = 0; nt < 8; nt++) {
                int n = n0 + wn * 64 + nt * 8 + cq * 2;
                int h = n >> 5, d = n & 31;
                __nv_bfloat16* oh = ohg + (size_t)(b * NH + h) * L * DK;
                __nv_bfloat16* ol = olg + (size_t)(b * NH + h) * L * DK;
#pragma unroll
                for (int rs = 0; rs < 2; rs++) {
                    int gm = m0 + wm * 32 + mt * 16 + gq + rs * 8;
                    unsigned hi, lo;
                    bsplit2(acc[mt][nt][rs * 2] * scale,
                            acc[mt][nt][rs * 2 + 1] * scale, hi, lo);
                    *(unsigned*)&oh[(size_t)gm * DK + d] = hi;
                    *(unsigned*)&ol[(size_t)gm * DK + d] = lo;
                }
            }
    } else {
#pragma unroll
        for (int mt = 0; mt < 2; mt++)
#pragma unroll
            for (int nt = 0; nt < 8; nt++) {
                int n = n0 + wn * 64 + nt * 8 + cq * 2;
                int h = n >> 5, d = n & 31;
                float* ov = g_vt + (size_t)(b * NH + h) * DV * L;
#pragma unroll
                for (int rs = 0; rs < 2; rs++) {
                    int gm = m0 + wm * 32 + mt * 16 + gq + rs * 8;
                    ov[(size_t)d * L + gm]       = tf32r(acc[mt][nt][rs * 2]);
                    ov[(size_t)(d + 1) * L + gm] = tf32r(acc[mt][nt][rs * 2 + 1]);
                }
            }
    }
}

// ---------------------------------------------------------------------------
// Kernel 2: flash attention, FAT WARPS: Br=256 per CTA (R11 winner, unchanged).
// ---------------------------------------------------------------------------
__global__ __launch_bounds__(256, 2) void attn_mma(const float* __restrict__ rel_bias)
{
    constexpr int KP = 40;   // bf16 pitch
    constexpr int VP = 68;   // fp32 pitch
    struct Tile {
        __nv_bfloat16 kh[64 * KP];   // 5120 B
        __nv_bfloat16 kl[64 * KP];   // 5120 B
        float         vt[32 * VP];   // 8704 B
    };
    __shared__ float bias_s[BIAS_W];
    __shared__ __align__(16) Tile tiles[2];

    const int bh = blockIdx.y;
    const int h  = bh & 7;
    const int b  = bh >> 3;
    const __nv_bfloat16* qh_g = g_qh + (size_t)bh * L * DK;
    const __nv_bfloat16* ql_g = g_ql + (size_t)bh * L * DK;
    const __nv_bfloat16* kh_g = g_kh + (size_t)bh * L * DK;
    const __nv_bfloat16* kl_g = g_kl + (size_t)bh * L * DK;
    const float*         vt_g = g_vt + (size_t)bh * DV * L;

    const int tid  = threadIdx.x;
    const int warp = tid >> 5;
    const int lane = tid & 31;
    const int g    = lane >> 2;
    const int c    = lane & 3;
    const int lt   = lane >> 3;
    const int lr   = lane & 7;
    const int i0   = blockIdx.x * 256;

    // Start tile-0 staging immediately (independent of q/bias loads).
    const int krow = tid >> 2, kc8 = (tid & 3) * 8;
    const int vd0  = tid >> 4, vj4 = (tid & 15) * 4;
    auto load_tile = [&](int j0, Tile& T) {
        cp16(&T.kh[krow * KP + kc8], &kh_g[(size_t)(j0 + krow) * DK + kc8]);
        cp16(&T.kl[krow * KP + kc8], &kl_g[(size_t)(j0 + krow) * DK + kc8]);
        cp16(&T.vt[vd0 * VP + vj4],        &vt_g[(size_t)vd0 * L + j0 + vj4]);
        cp16(&T.vt[(vd0 + 16) * VP + vj4], &vt_g[(size_t)(vd0 + 16) * L + j0 + vj4]);
    };
    load_tile(0, tiles[0]);
    cp_commit();

    // Compact Toeplitz bias window: idx = j - (i0+r) + 1056, r in [0,256).
    // Staged u = j - r + 255 in [0, 1278]; idx = u + (801 - i0).
    {
        const float* bsrc = rel_bias + (size_t)h * TBL + (801 - i0);
        for (int u = tid; u < BIAS_W; u += 256)
            bias_s[u] = bsrc[u] * LOG2E;
    }

    // q fragments direct from gmem (one-time LDG.32s)
    unsigned qh[2][2][4], ql[2][2][4];   // [mt][kc][frag]
#pragma unroll
    for (int mt = 0; mt < 2; mt++) {
        const int r0 = i0 + warp * 32 + mt * 16 + g;
#pragma unroll
        for (int kc = 0; kc < 2; kc++) {
            int col = kc * 16 + 2 * c;
            qh[mt][kc][0] = *(const unsigned*)&qh_g[(size_t)r0 * DK + col];
            qh[mt][kc][1] = *(const unsigned*)&qh_g[(size_t)(r0 + 8) * DK + col];
            qh[mt][kc][2] = *(const unsigned*)&qh_g[(size_t)r0 * DK + col + 8];
            qh[mt][kc][3] = *(const unsigned*)&qh_g[(size_t)(r0 + 8) * DK + col + 8];
            ql[mt][kc][0] = *(const unsigned*)&ql_g[(size_t)r0 * DK + col];
            ql[mt][kc][1] = *(const unsigned*)&ql_g[(size_t)(r0 + 8) * DK + col];
            ql[mt][kc][2] = *(const unsigned*)&ql_g[(size_t)r0 * DK + col + 8];
            ql[mt][kc][3] = *(const unsigned*)&ql_g[(size_t)(r0 + 8) * DK + col + 8];
        }
    }

    float lsum[2][2] = {};
    float o[2][4][4] = {};
    int ubase[2];
#pragma unroll
    for (int mt = 0; mt < 2; mt++)
        ubase[mt] = 255 - (warp * 32 + mt * 16 + g) + 2 * c;

    for (int jt = 0; jt < 16; jt++) {
        const int j0 = jt * 64;
        cp_wait<0>();
        __syncthreads();
        if (jt < 15) {
            load_tile(j0 + 64, tiles[(jt + 1) & 1]);
            cp_commit();
        }
        Tile& T = tiles[jt & 1];

#pragma unroll
        for (int half = 0; half < 2; half++) {
            float s[2][4][4];
#pragma unroll
            for (int mt = 0; mt < 2; mt++)
#pragma unroll
                for (int nt4 = 0; nt4 < 4; nt4++) {
                    int u0 = j0 + (half * 4 + nt4) * 8 + ubase[mt];
                    s[mt][nt4][0] = bias_s[u0];
                    s[mt][nt4][1] = bias_s[u0 + 1];
                    s[mt][nt4][2] = bias_s[u0 - 8];
                    s[mt][nt4][3] = bias_s[u0 - 7];
                }
#pragma unroll
            for (int kc = 0; kc < 2; kc++)
#pragma unroll
                for (int np2 = 0; np2 < 2; np2++) {
                    unsigned bhf[4], blf[4];
                    int row = (half * 2 + np2) * 16 + (lt >> 1) * 8 + lr;
                    int col = kc * 16 + (lt & 1) * 8;
                    ldsm4(bhf, smem_u32(&T.kh[row * KP + col]));
                    ldsm4(blf, smem_u32(&T.kl[row * KP + col]));
#pragma unroll
                    for (int mt = 0; mt < 2; mt++) {
                        float* sp0 = s[mt][np2 * 2];
                        float* sp1 = s[mt][np2 * 2 + 1];
                        mma_bf16(sp0, qh[mt][kc], bhf[0], bhf[1]);
                        mma_bf16(sp1, qh[mt][kc], bhf[2], bhf[3]);
                        mma_bf16(sp0, qh[mt][kc], blf[0], blf[1]);
                        mma_bf16(sp1, qh[mt][kc], blf[2], blf[3]);
                        mma_bf16(sp0, ql[mt][kc], bhf[0], bhf[1]);
                        mma_bf16(sp1, ql[mt][kc], bhf[2], bhf[3]);
                    }
                }

#pragma unroll
            for (int mt = 0; mt < 2; mt++)
#pragma unroll
                for (int nt4 = 0; nt4 < 4; nt4++) {
                    s[mt][nt4][0] = ex2f(s[mt][nt4][0]);
                    s[mt][nt4][1] = ex2f(s[mt][nt4][1]);
                    s[mt][nt4][2] = ex2f(s[mt][nt4][2]);
                    s[mt][nt4][3] = ex2f(s[mt][nt4][3]);
                    lsum[mt][0] += s[mt][nt4][0] + s[mt][nt4][1];
                    lsum[mt][1] += s[mt][nt4][2] + s[mt][nt4][3];
                }

#pragma unroll
            for (int j2 = 0; j2 < 4; j2++) {
                unsigned a0[4] = {__float_as_uint(s[0][j2][0]), __float_as_uint(s[0][j2][2]),
                                  __float_as_uint(s[0][j2][1]), __float_as_uint(s[0][j2][3])};
                unsigned a1[4] = {__float_as_uint(s[1][j2][0]), __float_as_uint(s[1][j2][2]),
                                  __float_as_uint(s[1][j2][1]), __float_as_uint(s[1][j2][3])};
#pragma unroll
                for (int dt = 0; dt < 4; dt++) {
                    float2 vv2 = *(const float2*)
                        &T.vt[(dt * 8 + g) * VP + half * 32 + j2 * 8 + 2 * c];
                    unsigned v0 = __float_as_uint(vv2.x), v1 = __float_as_uint(vv2.y);
                    mma_tf32(o[0][dt], a0, v0, v1);
                    mma_tf32(o[1][dt], a1, v0, v1);
                }
            }
        }
    }

#pragma unroll
    for (int mt = 0; mt < 2; mt++) {
        lsum[mt][0] += __shfl_xor_sync(0xffffffffu, lsum[mt][0], 1);
        lsum[mt][0] += __shfl_xor_sync(0xffffffffu, lsum[mt][0], 2);
        lsum[mt][1] += __shfl_xor_sync(0xffffffffu, lsum[mt][1], 1);
        lsum[mt][1] += __shfl_xor_sync(0xffffffffu, lsum[mt][1], 2);
        float inv0 = 1.0f / lsum[mt][0];
        float inv1 = 1.0f / lsum[mt][1];

        size_t row0 = (size_t)(b * L + i0 + warp * 32 + mt * 16 + g) * (NH * DV) + h * DV;
        size_t row1 = row0 + (size_t)8 * (NH * DV);
#pragma unroll
        for (int dt = 0; dt < 4; dt++) {
            unsigned hi, lo;
            bsplit2(o[mt][dt][0] * inv0, o[mt][dt][1] * inv0, hi, lo);
            *(unsigned*)&g_ah[row0 + dt * 8 + 2 * c] = hi;
            *(unsigned*)&g_al[row0 + dt * 8 + 2 * c] = lo;
            bsplit2(o[mt][dt][2] * inv1, o[mt][dt][3] * inv1, hi, lo);
            *(unsigned*)&g_ah[row1 + dt * 8 + 2 * c] = hi;
            *(unsigned*)&g_al[row1 + dt * 8 + 2 * c] = lo;
        }
    }
}

// ---------------------------------------------------------------------------
// Kernel 3: FF projection, fat bf16x3 gemm (128x128), fused bias +
// transposed store. grid (BL/128, 2).
// ---------------------------------------------------------------------------
__global__ __launch_bounds__(256, 2) void ff_mma(
    const float* __restrict__ ffb,
    float* __restrict__ out)
{
    extern __shared__ __align__(16) char dsm[];
    Gemm2Smem& S = *(Gemm2Smem*)dsm;

    const int m0 = blockIdx.x * 128;  // row in (B*L)
    const int n0 = blockIdx.y * 128;

    float acc[2][8][4] = {};
    gemm2_bf16x3(S, acc, g_ah, g_al, g_fh, g_fl, m0, n0);

    const int tid  = threadIdx.x;
    const int warp = tid >> 5;
    const int lane = tid & 31;
    const int gq   = lane >> 2;
    const int cq   = lane & 3;
    const int wm   = warp >> 1;
    const int wn   = warp & 1;

    const int bb  = m0 >> 10;
    const int l00 = m0 & 1023;
#pragma unroll
    for (int nt = 0; nt < 8; nt++)
#pragma unroll
        for (int e = 0; e < 2; e++) {
            int gn = n0 + wn * 64 + nt * 8 + cq * 2 + e;
            float bias = ffb[gn];
            float* dst = out + ((size_t)(bb * OUTC + gn)) * L + l00 + wm * 32;
#pragma unroll
            for (int mt = 0; mt < 2; mt++)
#pragma unroll
                for (int rs = 0; rs < 2; rs++)
                    dst[mt * 16 + rs * 8 + gq] = acc[mt][nt][rs * 2 + e] + bias;
        }
}

// ---------------------------------------------------------------------------
extern "C" void kernel_launch(void* const* d_in, const int* in_sizes, int n_in,
                              void* d_out, int out_size)
{
    const float* x        = (const float*)d_in[0];
    const float* Qw       = (const float*)d_in[1];
    const float* Kw       = (const float*)d_in[2];
    const float* Vw       = (const float*)d_in[3];
    const float* ffw      = (const float*)d_in[4];
    const float* ffb      = (const float*)d_in[5];
    const float* rel_bias = (const float*)d_in[6];
    float* out = (float*)d_out;

    cudaFuncSetAttribute(qkv_mma, cudaFuncAttributeMaxDynamicSharedMemorySize, GEMM2_SMEM);
    cudaFuncSetAttribute(ff_mma,  cudaFuncAttributeMaxDynamicSharedMemorySize, GEMM2_SMEM);

    prep_kernel<<<2048 + 256, 256>>>(x, Qw, Kw, Vw, ffw);
    qkv_mma<<<dim3(L / 128, 2, B * 3), 256, GEMM2_SMEM>>>();
    attn_mma<<<dim3(L / 256, B * NH), 256>>>(rel_bias);
    ff_mma<<<dim3((B * L) / 128, 2), 256, GEMM2_SMEM>>>(ffb, out);
}